// round 11
// baseline (speedup 1.0000x reference)
#include <cuda_runtime.h>
#include <cuda_bf16.h>
#include <cstdint>

#define Bb 256
#define Ss 512
#define Vv 50000
#define Dd 256
#define Ll 128
#define PAD_T 0
#define BOS_T 1
#define EOS_T 2

#define ROWB 528                      // B row bytes (k-major row: 256 bf16 + pad)
#define AROW 144                      // A chunk row bytes (64 bf16 + pad)
#define ACH  (128 * AROW)             // 18432 per A buffer
#define B_BYTES (256 * ROWB)          // 135168
#define SMEM_GEMM (B_BYTES + 2 * ACH) // 172032
#define STG_ROW 144                   // epilogue staging row bytes
#define BT 4                          // batches per klat block

// ---------------- device scratch ----------------
__device__ __nv_bfloat16 g_embWB[(size_t)Vv * Dd];  // bf16 emb@Wout
__device__ __nv_bfloat16 g_embB[(size_t)Vv * Dd];   // bf16 emb
__device__ float  g_enc[Bb * Dd];
__device__ float  g_c[Bb * Dd];
__device__ int    g_len[Bb];
__device__ int    g_mode;
__device__ int    g_valid;
__device__ int    g_done;
__device__ double g_sq;
__device__ double g_kl;

__device__ __forceinline__ uint32_t smem_u32(const void* p) {
    return (uint32_t)__cvta_generic_to_shared(p);
}

// ---------------- K0: detect mask dtype, zero enc + accumulators ------------
__global__ void k0_detect(const unsigned* mask_words) {
    {
        int i = blockIdx.x * 256 + threadIdx.x;
        ((float4*)g_enc)[i] = make_float4(0.f, 0.f, 0.f, 0.f);
    }
    if (blockIdx.x != 0) return;
    __shared__ int any_gt1, any_f32;
    if (threadIdx.x == 0) { any_gt1 = 0; any_f32 = 0; }
    __syncthreads();
    int bad = 0, f32 = 0;
    for (int i = threadIdx.x; i < 32768; i += 256) {
        unsigned v = mask_words[i];
        if (v > 1u) { bad = 1; if (v == 0x3f800000u) f32 = 1; }
    }
    if (bad) atomicOr(&any_gt1, 1);
    if (f32) atomicOr(&any_f32, 1);
    __syncthreads();
    if (threadIdx.x == 0) {
        g_mode = any_gt1 ? (any_f32 ? 2 : 1) : 0;
        g_sq = 0.0; g_kl = 0.0; g_valid = 0; g_done = 0;
    }
}
__device__ __forceinline__ int mask_at(const void* m, int idx, int mode) {
    if (mode == 0) return ((const int*)m)[idx] != 0;
    if (mode == 1) return ((const unsigned char*)m)[idx] != 0;
    return ((const float*)m)[idx] != 0.0f;
}

// ---------------- gemm_mma: 512 thr, 16 warps, 32x64 warp tiles (R8) --------
__global__ __launch_bounds__(512, 1)
void gemm_mma(const float* __restrict__ emb, const float* __restrict__ Wout) {
    extern __shared__ char sm[];
    char* smB = sm;                 // [k=256][ROWB]
    char* smA = sm + B_BYTES;       // 2 x [128][AROW]

    const int tid  = threadIdx.x;
    const int wid  = tid >> 5, lane = tid & 31;
    const int row0 = blockIdx.x * 128;

    // ---- B fill: fp32 Wout -> bf16 smem (k-major), coalesced ----
    {
        #pragma unroll
        for (int j = 0; j < 32; j++) {
            int u = tid + j * 512;              // < 16384 float4s
            float4 x = ((const float4*)Wout)[u];
            int k  = u >> 6;
            int n0 = (u & 63) * 4;
            __nv_bfloat162 p0 = __floats2bfloat162_rn(x.x, x.y);
            __nv_bfloat162 p1 = __floats2bfloat162_rn(x.z, x.w);
            *(uint2*)(smB + k * ROWB + n0 * 2) = make_uint2(*(uint32_t*)&p0, *(uint32_t*)&p1);
        }
    }

    float4 stage[4];
    // ---- load chunk 0 ----
    #pragma unroll
    for (int j = 0; j < 4; j++) {
        int u = tid + j * 512;
        int r = u >> 4, q = u & 15;
        stage[j] = (row0 + r < Vv)
                 ? *(const float4*)(emb + (size_t)(row0 + r) * Dd + q * 4)
                 : make_float4(0.f, 0.f, 0.f, 0.f);
    }
    #pragma unroll
    for (int j = 0; j < 4; j++) {
        int u = tid + j * 512;
        int r = u >> 4, q = u & 15;
        __nv_bfloat162 p0 = __floats2bfloat162_rn(stage[j].x, stage[j].y);
        __nv_bfloat162 p1 = __floats2bfloat162_rn(stage[j].z, stage[j].w);
        uint2 pv = make_uint2(*(uint32_t*)&p0, *(uint32_t*)&p1);
        *(uint2*)(smA + r * AROW + q * 8) = pv;
        if (row0 + r < Vv)
            *(uint2*)(g_embB + (size_t)(row0 + r) * Dd + q * 4) = pv;
    }
    __syncthreads();

    const int wm = wid & 3, wn = wid >> 2;
    float acc[2][8][4];
    #pragma unroll
    for (int mt = 0; mt < 2; mt++)
        #pragma unroll
        for (int nt = 0; nt < 8; nt++)
            #pragma unroll
            for (int e = 0; e < 4; e++) acc[mt][nt][e] = 0.0f;

    const uint32_t aBase = smem_u32(smA) + (wm * 32 + (lane & 15)) * AROW + (lane >> 4) * 16;
    const uint32_t bBase = smem_u32(smB) + (lane & 15) * ROWB
                         + (wn * 64 + (lane >> 4) * 8) * 2;

    for (int c = 0; c < 4; c++) {
        if (c < 3) {
            #pragma unroll
            for (int j = 0; j < 4; j++) {
                int u = tid + j * 512;
                int r = u >> 4, q = u & 15;
                stage[j] = (row0 + r < Vv)
                         ? *(const float4*)(emb + (size_t)(row0 + r) * Dd + (c + 1) * 64 + q * 4)
                         : make_float4(0.f, 0.f, 0.f, 0.f);
            }
        }
        const uint32_t abuf = aBase + (c & 1) * ACH;
        const uint32_t bko  = (uint32_t)(c * 64) * ROWB;
        #pragma unroll
        for (int ks = 0; ks < 4; ks++) {
            uint32_t a[2][4];
            #pragma unroll
            for (int mt = 0; mt < 2; mt++)
                asm volatile("ldmatrix.sync.aligned.m8n8.x4.shared.b16 {%0,%1,%2,%3}, [%4];"
                             : "=r"(a[mt][0]), "=r"(a[mt][1]), "=r"(a[mt][2]), "=r"(a[mt][3])
                             : "r"(abuf + mt * 16 * AROW + ks * 32));
            #pragma unroll
            for (int np = 0; np < 4; np++) {
                uint32_t b0, b1, b2, b3;
                asm volatile("ldmatrix.sync.aligned.m8n8.x4.trans.shared.b16 {%0,%1,%2,%3}, [%4];"
                             : "=r"(b0), "=r"(b1), "=r"(b2), "=r"(b3)
                             : "r"(bBase + bko + ks * 16 * ROWB + np * 32));
                #pragma unroll
                for (int mt = 0; mt < 2; mt++) {
                    float* c0 = acc[mt][2 * np];
                    asm volatile("mma.sync.aligned.m16n8k16.row.col.f32.bf16.bf16.f32 "
                                 "{%0,%1,%2,%3}, {%4,%5,%6,%7}, {%8,%9}, {%0,%1,%2,%3};"
                                 : "+f"(c0[0]), "+f"(c0[1]), "+f"(c0[2]), "+f"(c0[3])
                                 : "r"(a[mt][0]), "r"(a[mt][1]), "r"(a[mt][2]), "r"(a[mt][3]),
                                   "r"(b0), "r"(b1));
                    float* c1 = acc[mt][2 * np + 1];
                    asm volatile("mma.sync.aligned.m16n8k16.row.col.f32.bf16.bf16.f32 "
                                 "{%0,%1,%2,%3}, {%4,%5,%6,%7}, {%8,%9}, {%0,%1,%2,%3};"
                                 : "+f"(c1[0]), "+f"(c1[1]), "+f"(c1[2]), "+f"(c1[3])
                                 : "r"(a[mt][0]), "r"(a[mt][1]), "r"(a[mt][2]), "r"(a[mt][3]),
                                   "r"(b2), "r"(b3));
                }
            }
        }
        if (c < 3) {
            __syncthreads();
            char* dst = smA + ((c + 1) & 1) * ACH;
            #pragma unroll
            for (int j = 0; j < 4; j++) {
                int u = tid + j * 512;
                int r = u >> 4, q = u & 15;
                __nv_bfloat162 p0 = __floats2bfloat162_rn(stage[j].x, stage[j].y);
                __nv_bfloat162 p1 = __floats2bfloat162_rn(stage[j].z, stage[j].w);
                uint2 pv = make_uint2(*(uint32_t*)&p0, *(uint32_t*)&p1);
                *(uint2*)(dst + r * AROW + q * 8) = pv;
                if (row0 + r < Vv)
                    *(uint2*)(g_embB + (size_t)(row0 + r) * Dd + (c + 1) * 64 + q * 4) = pv;
            }
            __syncthreads();
        }
    }

    // ---- epilogue: stage per-warp 32x64 bf16 tile in smem, dense stores ----
    {
        char* stg = smB + wid * 32 * STG_ROW;
        const int colq = (lane & 3) * 2;
        const int rowq = lane >> 2;
        #pragma unroll
        for (int mt = 0; mt < 2; mt++) {
            #pragma unroll
            for (int nt = 0; nt < 8; nt++) {
                __nv_bfloat162 lo = __floats2bfloat162_rn(acc[mt][nt][0], acc[mt][nt][1]);
                __nv_bfloat162 hi = __floats2bfloat162_rn(acc[mt][nt][2], acc[mt][nt][3]);
                *(uint32_t*)(stg + (mt * 16 + rowq) * STG_ROW + (nt * 8 + colq) * 2) = *(uint32_t*)&lo;
                *(uint32_t*)(stg + (mt * 16 + rowq + 8) * STG_ROW + (nt * 8 + colq) * 2) = *(uint32_t*)&hi;
            }
        }
        __syncwarp();
        #pragma unroll
        for (int p = 0; p < 8; p++) {
            int row = p * 4 + (lane >> 3);
            int q = lane & 7;
            uint4 v = *(const uint4*)(stg + row * STG_ROW + q * 16);
            int gr = row0 + wm * 32 + row;
            if (gr < Vv)
                *(uint4*)(g_embWB + (size_t)gr * Dd + wn * 64 + q * 8) = v;
        }
    }
}

// ---------------- enc_par: partial masked sums, grid (Bb, 8) ---------------
__global__ void enc_par(const int* __restrict__ vocab,
                        const int* __restrict__ order,
                        const void* __restrict__ mask,
                        const float* __restrict__ emb) {
    const int b = blockIdx.x;
    const int part = blockIdx.y;
    const int tid = threadIdx.x;
    const int w = tid >> 5, lane = tid & 31;
    const int mode = g_mode;

    __shared__ int sred[256];
    __shared__ int s_len;

    int cnt = 0;
    for (int i = tid; i < Ss; i += 256) cnt += mask_at(mask, b * Ss + i, mode);
    sred[tid] = cnt;
    __syncthreads();
    for (int st = 128; st > 0; st >>= 1) {
        if (tid < st) sred[tid] += sred[tid + st];
        __syncthreads();
    }
    if (tid == 0) {
        int len = sred[0];
        s_len = len;
        if (part == 0) {
            g_len[b] = len;
            atomicAdd(&g_valid, (len < Ss) ? len + 1 : Ss + 1);
        }
    }
    __syncthreads();
    const int len = s_len;

    float a0 = 0, a1 = 0, a2 = 0, a3 = 0, a4 = 0, a5 = 0, a6 = 0, a7 = 0;
    for (int s = part * 8 + w; s < len; s += 64) {
        int tok = vocab[b * Ss + s];
        int oi = order[(size_t)(b * Ss + s) * 6];
        if (oi == -1) oi = BOS_T;
        int p;
        if (s == 0) p = BOS_T;
        else        p = (oi < len) ? vocab[b * Ss + oi] : PAD_T;
        const float* r1 = emb + (size_t)tok * Dd + lane * 8;
        const float* r2 = emb + (size_t)p   * Dd + lane * 8;
        float4 x0 = *(const float4*)r1;
        float4 x1 = *(const float4*)(r1 + 4);
        float4 y0 = *(const float4*)r2;
        float4 y1 = *(const float4*)(r2 + 4);
        a0 += x0.x + y0.x; a1 += x0.y + y0.y; a2 += x0.z + y0.z; a3 += x0.w + y0.w;
        a4 += x1.x + y1.x; a5 += x1.y + y1.y; a6 += x1.z + y1.z; a7 += x1.w + y1.w;
    }
    __shared__ float s_acc[8][256];
    float* dst = &s_acc[w][lane * 8];
    dst[0] = a0; dst[1] = a1; dst[2] = a2; dst[3] = a3;
    dst[4] = a4; dst[5] = a5; dst[6] = a6; dst[7] = a7;
    __syncthreads();
    float v = 0;
    #pragma unroll
    for (int ww = 0; ww < 8; ww++) v += s_acc[ww][tid];
    atomicAdd(&g_enc[b * Dd + tid], v);
}

// ---------------- klat2: 4 batches/block, grid 64 ----------------------------
// Phase1: thread t<128 -> mean col t, t>=128 -> lv col t-128, for BT batches.
// Then z+kl, memory = z@Wlin+blin, c = memory@Wout+bout.
__global__ __launch_bounds__(256)
void klat_kernel(const float* __restrict__ eps,
                 const float* __restrict__ Wm, const float* __restrict__ bm,
                 const float* __restrict__ Wv, const float* __restrict__ bv,
                 const float* __restrict__ Wlin, const float* __restrict__ blin,
                 const float* __restrict__ Wout, const float* __restrict__ bout) {
    const int t = threadIdx.x;
    const int b0 = blockIdx.x * BT;

    __shared__ float se[BT][Dd];       // enc (mean-normalized)
    __shared__ float sml[2][BT][Ll];   // [0]=mean, [1]=lv
    __shared__ float sz[BT][Ll];       // z
    __shared__ float sme[BT][Dd];      // memory
    __shared__ float skl[8];

    // load enc for BT batches
    #pragma unroll
    for (int i = 0; i < BT; i++) {
        float inv = 1.0f / (float)g_len[b0 + i];
        se[i][t] = g_enc[(b0 + i) * Dd + t] * inv;
    }
    __syncthreads();

    // phase 1: mean / lv
    {
        const int tt = t & (Ll - 1);
        const float* W = (t < Ll) ? Wm : Wv;
        const float bias = (t < Ll) ? bm[tt] : bv[tt];
        float acc[BT];
        #pragma unroll
        for (int i = 0; i < BT; i++) acc[i] = bias;
        for (int d = 0; d < Dd; d++) {
            float w = W[d * Ll + tt];
            #pragma unroll
            for (int i = 0; i < BT; i++) acc[i] += se[i][d] * w;
        }
        const int half = t >> 7;   // 0=mean, 1=lv
        #pragma unroll
        for (int i = 0; i < BT; i++) sml[half][i][tt] = acc[i];
    }
    __syncthreads();

    // phase 2: z + kl (threads t<128)
    float klp = 0.0f;
    if (t < Ll) {
        #pragma unroll
        for (int i = 0; i < BT; i++) {
            float mean = sml[0][i][t], lv = sml[1][i][t];
            sz[i][t] = mean + eps[(b0 + i) * Ll + t] * expf(0.5f * lv);
            klp += 1.0f + lv - mean * mean - expf(lv);
        }
    }
    #pragma unroll
    for (int off = 16; off > 0; off >>= 1)
        klp += __shfl_xor_sync(0xffffffffu, klp, off);
    if ((t & 31) == 0) skl[t >> 5] = klp;
    __syncthreads();
    if (t == 0)
        atomicAdd(&g_kl, (double)(skl[0] + skl[1] + skl[2] + skl[3] +
                                  skl[4] + skl[5] + skl[6] + skl[7]));

    // phase 3: memory[i][t] = blin[t] + sum_l z[i][l]*Wlin[l][t]
    {
        float acc[BT];
        const float bias = blin[t];
        #pragma unroll
        for (int i = 0; i < BT; i++) acc[i] = bias;
        for (int l = 0; l < Ll; l++) {
            float w = Wlin[l * Dd + t];
            #pragma unroll
            for (int i = 0; i < BT; i++) acc[i] += sz[i][l] * w;
        }
        #pragma unroll
        for (int i = 0; i < BT; i++) sme[i][t] = acc[i];
    }
    __syncthreads();

    // phase 4: c[i][t] = bout[t] + sum_k memory[i][k]*Wout[k][t]
    {
        float acc[BT];
        const float bias = bout[t];
        #pragma unroll
        for (int i = 0; i < BT; i++) acc[i] = bias;
        for (int k = 0; k < Dd; k++) {
            float w = Wout[(size_t)k * Dd + t];
            #pragma unroll
            for (int i = 0; i < BT; i++) acc[i] += sme[i][k] * w;
        }
        #pragma unroll
        for (int i = 0; i < BT; i++) g_c[(b0 + i) * Dd + t] = acc[i];
    }
}

// ---------------- loss reduction + fused finalize ---------------------------
__global__ void loss_kernel(const int* __restrict__ vocab, float* __restrict__ out) {
    const int b = blockIdx.x;
    const int chunk = blockIdx.y;
    const int tid = threadIdx.x;
    const int w = tid >> 5, lane = tid & 31;
    const int len = g_len[b];
    const int nb = (len < Ss) ? len + 1 : Ss + 1;

    const float* crow = g_c + b * Dd + lane * 8;
    float4 c0 = *(const float4*)crow;
    float4 c1 = *(const float4*)(crow + 4);

    float ss = 0.0f;
    for (int s = chunk * 8 + w; s < nb; s += 64) {
        int u = (s == 0) ? BOS_T : vocab[b * Ss + s - 1];
        int v;
        if (s < len) v = vocab[b * Ss + s];
        else         v = (len < Ss) ? EOS_T : BOS_T;
        uint4 araw = *(const uint4*)(g_embWB + (size_t)u * Dd + lane * 8);
        uint4 traw = *(const uint4*)(g_embB  + (size_t)v * Dd + lane * 8);
        const __nv_bfloat162* ap = (const __nv_bfloat162*)&araw;
        const __nv_bfloat162* tp = (const __nv_bfloat162*)&traw;
        float2 f0 = __bfloat1622float2(ap[0]);
        float2 f1 = __bfloat1622float2(ap[1]);
        float2 f2 = __bfloat1622float2(ap[2]);
        float2 f3 = __bfloat1622float2(ap[3]);
        float2 t0 = __bfloat1622float2(tp[0]);
        float2 t1 = __bfloat1622float2(tp[1]);
        float2 t2 = __bfloat1622float2(tp[2]);
        float2 t3 = __bfloat1622float2(tp[3]);
        float d0 = f0.x + c0.x - t0.x; ss += d0 * d0;
        float d1 = f0.y + c0.y - t0.y; ss += d1 * d1;
        float d2 = f1.x + c0.z - t1.x; ss += d2 * d2;
        float d3 = f1.y + c0.w - t1.y; ss += d3 * d3;
        float d4 = f2.x + c1.x - t2.x; ss += d4 * d4;
        float d5 = f2.y + c1.y - t2.y; ss += d5 * d5;
        float d6 = f3.x + c1.z - t3.x; ss += d6 * d6;
        float d7 = f3.y + c1.w - t3.y; ss += d7 * d7;
    }
    #pragma unroll
    for (int off = 16; off > 0; off >>= 1)
        ss += __shfl_xor_sync(0xffffffffu, ss, off);
    __shared__ float swarp[8];
    if (lane == 0) swarp[w] = ss;
    __syncthreads();
    if (tid == 0) {
        double tot = 0.0;
        #pragma unroll
        for (int i = 0; i < 8; i++) tot += (double)swarp[i];
        atomicAdd(&g_sq, tot);
        __threadfence();
        int done = atomicAdd(&g_done, 1);
        if (done == Bb * 8 - 1) {
            double sq = atomicAdd(&g_sq, 0.0);
            double kl = atomicAdd(&g_kl, 0.0);
            int valid = atomicAdd(&g_valid, 0);
            long long denom = (long long)valid * (long long)Dd;
            if (denom < 1) denom = 1;
            out[0] = (float)(sq / (double)denom);
            out[1] = (float)(-0.5 * kl / (double)Bb);
        }
    }
}

// ---------------- launch ----------------------------------------------------
extern "C" void kernel_launch(void* const* d_in, const int* in_sizes, int n_in,
                              void* d_out, int out_size) {
    (void)in_sizes; (void)n_in; (void)out_size;
    const int*   vocab = (const int*)d_in[0];
    const int*   order = (const int*)d_in[1];
    const void*  mask  = d_in[2];
    const float* eps   = (const float*)d_in[3];
    const float* emb   = (const float*)d_in[4];
    const float* Wm    = (const float*)d_in[5];
    const float* bm    = (const float*)d_in[6];
    const float* Wv    = (const float*)d_in[7];
    const float* bv    = (const float*)d_in[8];
    const float* Wlin  = (const float*)d_in[9];
    const float* blin  = (const float*)d_in[10];
    const float* Wout  = (const float*)d_in[11];
    const float* bout  = (const float*)d_in[12];
    float* out = (float*)d_out;

    static cudaStream_t s2 = nullptr;
    static cudaEvent_t ev_fork = nullptr, ev_join = nullptr;
    static int configured = 0;
    if (!configured) {
        cudaFuncSetAttribute(gemm_mma, cudaFuncAttributeMaxDynamicSharedMemorySize, SMEM_GEMM);
        cudaStreamCreateWithFlags(&s2, cudaStreamNonBlocking);
        cudaEventCreateWithFlags(&ev_fork, cudaEventDisableTiming);
        cudaEventCreateWithFlags(&ev_join, cudaEventDisableTiming);
        configured = 1;
    }

    cudaEventRecord(ev_fork, 0);

    // main stream: GEMM path launched first so it leads the replay
    gemm_mma<<<(Vv + 127) / 128, 512, SMEM_GEMM>>>(emb, Wout);

    // side stream: k0 + enc chain (independent of GEMM)
    cudaStreamWaitEvent(s2, ev_fork, 0);
    k0_detect<<<64, 256, 0, s2>>>((const unsigned*)mask);
    enc_par<<<dim3(Bb, 8), 256, 0, s2>>>(vocab, order, mask, emb);
    klat_kernel<<<Bb / BT, 256, 0, s2>>>(eps, Wm, bm, Wv, bv, Wlin, blin, Wout, bout);
    cudaEventRecord(ev_join, s2);

    cudaStreamWaitEvent(0, ev_join, 0);
    loss_kernel<<<dim3(Bb, 8), 256>>>(vocab, out);
}

// round 12
// speedup vs baseline: 1.0430x; 1.0430x over previous
#include <cuda_runtime.h>
#include <cuda_bf16.h>
#include <cstdint>

#define Bb 256
#define Ss 512
#define Vv 50000
#define Dd 256
#define Ll 128
#define PAD_T 0
#define BOS_T 1
#define EOS_T 2

#define ROWB 528                      // B row bytes (k-major row: 256 bf16 + pad)
#define AROW 144                      // A chunk row bytes (64 bf16 + pad)
#define ACH  (128 * AROW)             // 18432 per A buffer
#define B_BYTES (256 * ROWB)          // 135168
#define SMEM_GEMM (B_BYTES + 2 * ACH) // 172032
#define STG_ROW 144                   // epilogue staging row bytes

// ---------------- device scratch ----------------
__device__ __nv_bfloat16 g_embWB[(size_t)Vv * Dd];  // bf16 emb@Wout
__device__ __nv_bfloat16 g_embB[(size_t)Vv * Dd];   // bf16 emb
__device__ float  g_enc[Bb * Dd];
__device__ float  g_c[Bb * Dd];
__device__ int    g_len[Bb];
__device__ int    g_mode;
__device__ int    g_valid;
__device__ int    g_done;
__device__ double g_sq;
__device__ double g_kl;

__device__ __forceinline__ uint32_t smem_u32(const void* p) {
    return (uint32_t)__cvta_generic_to_shared(p);
}

// ---------------- K0: detect mask dtype, zero enc + accumulators ------------
__global__ void k0_detect(const unsigned* mask_words) {
    {
        int i = blockIdx.x * 256 + threadIdx.x;
        ((float4*)g_enc)[i] = make_float4(0.f, 0.f, 0.f, 0.f);
    }
    if (blockIdx.x != 0) return;
    __shared__ int any_gt1, any_f32;
    if (threadIdx.x == 0) { any_gt1 = 0; any_f32 = 0; }
    __syncthreads();
    int bad = 0, f32 = 0;
    for (int i = threadIdx.x; i < 32768; i += 256) {
        unsigned v = mask_words[i];
        if (v > 1u) { bad = 1; if (v == 0x3f800000u) f32 = 1; }
    }
    if (bad) atomicOr(&any_gt1, 1);
    if (f32) atomicOr(&any_f32, 1);
    __syncthreads();
    if (threadIdx.x == 0) {
        g_mode = any_gt1 ? (any_f32 ? 2 : 1) : 0;
        g_sq = 0.0; g_kl = 0.0; g_valid = 0; g_done = 0;
    }
}
__device__ __forceinline__ int mask_at(const void* m, int idx, int mode) {
    if (mode == 0) return ((const int*)m)[idx] != 0;
    if (mode == 1) return ((const unsigned char*)m)[idx] != 0;
    return ((const float*)m)[idx] != 0.0f;
}

// ---------------- gemm_mma: 512 thr, 16 warps, 32x64 warp tiles (R8) --------
__global__ __launch_bounds__(512, 1)
void gemm_mma(const float* __restrict__ emb, const float* __restrict__ Wout) {
    extern __shared__ char sm[];
    char* smB = sm;                 // [k=256][ROWB]
    char* smA = sm + B_BYTES;       // 2 x [128][AROW]

    const int tid  = threadIdx.x;
    const int wid  = tid >> 5, lane = tid & 31;
    const int row0 = blockIdx.x * 128;

    // ---- B fill: fp32 Wout -> bf16 smem (k-major), coalesced ----
    {
        #pragma unroll
        for (int j = 0; j < 32; j++) {
            int u = tid + j * 512;              // < 16384 float4s
            float4 x = ((const float4*)Wout)[u];
            int k  = u >> 6;
            int n0 = (u & 63) * 4;
            __nv_bfloat162 p0 = __floats2bfloat162_rn(x.x, x.y);
            __nv_bfloat162 p1 = __floats2bfloat162_rn(x.z, x.w);
            *(uint2*)(smB + k * ROWB + n0 * 2) = make_uint2(*(uint32_t*)&p0, *(uint32_t*)&p1);
        }
    }

    float4 stage[4];
    // ---- load chunk 0 ----
    #pragma unroll
    for (int j = 0; j < 4; j++) {
        int u = tid + j * 512;
        int r = u >> 4, q = u & 15;
        stage[j] = (row0 + r < Vv)
                 ? *(const float4*)(emb + (size_t)(row0 + r) * Dd + q * 4)
                 : make_float4(0.f, 0.f, 0.f, 0.f);
    }
    #pragma unroll
    for (int j = 0; j < 4; j++) {
        int u = tid + j * 512;
        int r = u >> 4, q = u & 15;
        __nv_bfloat162 p0 = __floats2bfloat162_rn(stage[j].x, stage[j].y);
        __nv_bfloat162 p1 = __floats2bfloat162_rn(stage[j].z, stage[j].w);
        uint2 pv = make_uint2(*(uint32_t*)&p0, *(uint32_t*)&p1);
        *(uint2*)(smA + r * AROW + q * 8) = pv;
        if (row0 + r < Vv)
            *(uint2*)(g_embB + (size_t)(row0 + r) * Dd + q * 4) = pv;
    }
    __syncthreads();

    const int wm = wid & 3, wn = wid >> 2;
    float acc[2][8][4];
    #pragma unroll
    for (int mt = 0; mt < 2; mt++)
        #pragma unroll
        for (int nt = 0; nt < 8; nt++)
            #pragma unroll
            for (int e = 0; e < 4; e++) acc[mt][nt][e] = 0.0f;

    const uint32_t aBase = smem_u32(smA) + (wm * 32 + (lane & 15)) * AROW + (lane >> 4) * 16;
    const uint32_t bBase = smem_u32(smB) + (lane & 15) * ROWB
                         + (wn * 64 + (lane >> 4) * 8) * 2;

    for (int c = 0; c < 4; c++) {
        if (c < 3) {
            #pragma unroll
            for (int j = 0; j < 4; j++) {
                int u = tid + j * 512;
                int r = u >> 4, q = u & 15;
                stage[j] = (row0 + r < Vv)
                         ? *(const float4*)(emb + (size_t)(row0 + r) * Dd + (c + 1) * 64 + q * 4)
                         : make_float4(0.f, 0.f, 0.f, 0.f);
            }
        }
        const uint32_t abuf = aBase + (c & 1) * ACH;
        const uint32_t bko  = (uint32_t)(c * 64) * ROWB;
        #pragma unroll
        for (int ks = 0; ks < 4; ks++) {
            uint32_t a[2][4];
            #pragma unroll
            for (int mt = 0; mt < 2; mt++)
                asm volatile("ldmatrix.sync.aligned.m8n8.x4.shared.b16 {%0,%1,%2,%3}, [%4];"
                             : "=r"(a[mt][0]), "=r"(a[mt][1]), "=r"(a[mt][2]), "=r"(a[mt][3])
                             : "r"(abuf + mt * 16 * AROW + ks * 32));
            #pragma unroll
            for (int np = 0; np < 4; np++) {
                uint32_t b0, b1, b2, b3;
                asm volatile("ldmatrix.sync.aligned.m8n8.x4.trans.shared.b16 {%0,%1,%2,%3}, [%4];"
                             : "=r"(b0), "=r"(b1), "=r"(b2), "=r"(b3)
                             : "r"(bBase + bko + ks * 16 * ROWB + np * 32));
                #pragma unroll
                for (int mt = 0; mt < 2; mt++) {
                    float* c0 = acc[mt][2 * np];
                    asm volatile("mma.sync.aligned.m16n8k16.row.col.f32.bf16.bf16.f32 "
                                 "{%0,%1,%2,%3}, {%4,%5,%6,%7}, {%8,%9}, {%0,%1,%2,%3};"
                                 : "+f"(c0[0]), "+f"(c0[1]), "+f"(c0[2]), "+f"(c0[3])
                                 : "r"(a[mt][0]), "r"(a[mt][1]), "r"(a[mt][2]), "r"(a[mt][3]),
                                   "r"(b0), "r"(b1));
                    float* c1 = acc[mt][2 * np + 1];
                    asm volatile("mma.sync.aligned.m16n8k16.row.col.f32.bf16.bf16.f32 "
                                 "{%0,%1,%2,%3}, {%4,%5,%6,%7}, {%8,%9}, {%0,%1,%2,%3};"
                                 : "+f"(c1[0]), "+f"(c1[1]), "+f"(c1[2]), "+f"(c1[3])
                                 : "r"(a[mt][0]), "r"(a[mt][1]), "r"(a[mt][2]), "r"(a[mt][3]),
                                   "r"(b2), "r"(b3));
                }
            }
        }
        if (c < 3) {
            __syncthreads();
            char* dst = smA + ((c + 1) & 1) * ACH;
            #pragma unroll
            for (int j = 0; j < 4; j++) {
                int u = tid + j * 512;
                int r = u >> 4, q = u & 15;
                __nv_bfloat162 p0 = __floats2bfloat162_rn(stage[j].x, stage[j].y);
                __nv_bfloat162 p1 = __floats2bfloat162_rn(stage[j].z, stage[j].w);
                uint2 pv = make_uint2(*(uint32_t*)&p0, *(uint32_t*)&p1);
                *(uint2*)(dst + r * AROW + q * 8) = pv;
                if (row0 + r < Vv)
                    *(uint2*)(g_embB + (size_t)(row0 + r) * Dd + (c + 1) * 64 + q * 4) = pv;
            }
            __syncthreads();
        }
    }

    // ---- epilogue: stage per-warp 32x64 bf16 tile in smem, dense stores ----
    {
        char* stg = smB + wid * 32 * STG_ROW;
        const int colq = (lane & 3) * 2;
        const int rowq = lane >> 2;
        #pragma unroll
        for (int mt = 0; mt < 2; mt++) {
            #pragma unroll
            for (int nt = 0; nt < 8; nt++) {
                __nv_bfloat162 lo = __floats2bfloat162_rn(acc[mt][nt][0], acc[mt][nt][1]);
                __nv_bfloat162 hi = __floats2bfloat162_rn(acc[mt][nt][2], acc[mt][nt][3]);
                *(uint32_t*)(stg + (mt * 16 + rowq) * STG_ROW + (nt * 8 + colq) * 2) = *(uint32_t*)&lo;
                *(uint32_t*)(stg + (mt * 16 + rowq + 8) * STG_ROW + (nt * 8 + colq) * 2) = *(uint32_t*)&hi;
            }
        }
        __syncwarp();
        #pragma unroll
        for (int p = 0; p < 8; p++) {
            int row = p * 4 + (lane >> 3);
            int q = lane & 7;
            uint4 v = *(const uint4*)(stg + row * STG_ROW + q * 16);
            int gr = row0 + wm * 32 + row;
            if (gr < Vv)
                *(uint4*)(g_embWB + (size_t)gr * Dd + wn * 64 + q * 8) = v;
        }
    }
}

// ---------------- enc_par: partial masked sums, grid (Bb, 8) ---------------
__global__ void enc_par(const int* __restrict__ vocab,
                        const int* __restrict__ order,
                        const void* __restrict__ mask,
                        const float* __restrict__ emb) {
    const int b = blockIdx.x;
    const int part = blockIdx.y;
    const int tid = threadIdx.x;
    const int w = tid >> 5, lane = tid & 31;
    const int mode = g_mode;

    __shared__ int sred[256];
    __shared__ int s_len;

    int cnt = 0;
    for (int i = tid; i < Ss; i += 256) cnt += mask_at(mask, b * Ss + i, mode);
    sred[tid] = cnt;
    __syncthreads();
    for (int st = 128; st > 0; st >>= 1) {
        if (tid < st) sred[tid] += sred[tid + st];
        __syncthreads();
    }
    if (tid == 0) {
        int len = sred[0];
        s_len = len;
        if (part == 0) {
            g_len[b] = len;
            atomicAdd(&g_valid, (len < Ss) ? len + 1 : Ss + 1);
        }
    }
    __syncthreads();
    const int len = s_len;

    float a0 = 0, a1 = 0, a2 = 0, a3 = 0, a4 = 0, a5 = 0, a6 = 0, a7 = 0;
    for (int s = part * 8 + w; s < len; s += 64) {
        int tok = vocab[b * Ss + s];
        int oi = order[(size_t)(b * Ss + s) * 6];
        if (oi == -1) oi = BOS_T;
        int p;
        if (s == 0) p = BOS_T;
        else        p = (oi < len) ? vocab[b * Ss + oi] : PAD_T;
        const float* r1 = emb + (size_t)tok * Dd + lane * 8;
        const float* r2 = emb + (size_t)p   * Dd + lane * 8;
        float4 x0 = *(const float4*)r1;
        float4 x1 = *(const float4*)(r1 + 4);
        float4 y0 = *(const float4*)r2;
        float4 y1 = *(const float4*)(r2 + 4);
        a0 += x0.x + y0.x; a1 += x0.y + y0.y; a2 += x0.z + y0.z; a3 += x0.w + y0.w;
        a4 += x1.x + y1.x; a5 += x1.y + y1.y; a6 += x1.z + y1.z; a7 += x1.w + y1.w;
    }
    __shared__ float s_acc[8][256];
    float* dst = &s_acc[w][lane * 8];
    dst[0] = a0; dst[1] = a1; dst[2] = a2; dst[3] = a3;
    dst[4] = a4; dst[5] = a5; dst[6] = a6; dst[7] = a7;
    __syncthreads();
    float v = 0;
    #pragma unroll
    for (int ww = 0; ww < 8; ww++) v += s_acc[ww][tid];
    atomicAdd(&g_enc[b * Dd + tid], v);
}

// ---------------- klat: grid Bb, 16-way MLP in every GEMV phase -------------
__global__ __launch_bounds__(256)
void klat_kernel(const float* __restrict__ eps,
                 const float* __restrict__ Wm, const float* __restrict__ bm,
                 const float* __restrict__ Wv, const float* __restrict__ bv,
                 const float* __restrict__ Wlin, const float* __restrict__ blin,
                 const float* __restrict__ Wout, const float* __restrict__ bout) {
    const int b = blockIdx.x, t = threadIdx.x;
    __shared__ float se[Dd];
    __shared__ float smean[Ll], slv[Ll], sz[Ll], smem_[Dd];
    __shared__ float skl[8];

    const float inv = 1.0f / (float)g_len[b];
    se[t] = g_enc[b * Dd + t] * inv;
    __syncthreads();

    // phase 1: mean (t<128) / log_var (t>=128), 16 independent chains
    {
        const int tt = t & (Ll - 1);
        const float* W = (t < Ll) ? Wm : Wv;
        float acc[16];
        #pragma unroll
        for (int j = 0; j < 16; j++) acc[j] = 0.0f;
        #pragma unroll
        for (int d = 0; d < Dd; d += 16) {
            #pragma unroll
            for (int j = 0; j < 16; j++)
                acc[j] += se[d + j] * __ldg(&W[(d + j) * Ll + tt]);
        }
        float r = ((t < Ll) ? bm[tt] : bv[tt]);
        #pragma unroll
        for (int j = 0; j < 16; j++) r += acc[j];
        if (t < Ll) smean[tt] = r; else slv[tt] = r;
    }
    __syncthreads();

    // phase 2: z + kl (t<128)
    float klp = 0.0f;
    if (t < Ll) {
        float mean = smean[t], lv = slv[t];
        sz[t] = mean + eps[b * Ll + t] * expf(0.5f * lv);
        klp = 1.0f + lv - mean * mean - expf(lv);
    }
    #pragma unroll
    for (int off = 16; off > 0; off >>= 1)
        klp += __shfl_xor_sync(0xffffffffu, klp, off);
    if ((t & 31) == 0) skl[t >> 5] = klp;
    __syncthreads();
    if (t == 0)
        atomicAdd(&g_kl, (double)(skl[0] + skl[1] + skl[2] + skl[3] +
                                  skl[4] + skl[5] + skl[6] + skl[7]));

    // phase 3: memory[t] = blin[t] + sum_l z[l]*Wlin[l][t]  (16 chains)
    {
        float acc[16];
        #pragma unroll
        for (int j = 0; j < 16; j++) acc[j] = 0.0f;
        #pragma unroll
        for (int l = 0; l < Ll; l += 16) {
            #pragma unroll
            for (int j = 0; j < 16; j++)
                acc[j] += sz[l + j] * __ldg(&Wlin[(l + j) * Dd + t]);
        }
        float r = blin[t];
        #pragma unroll
        for (int j = 0; j < 16; j++) r += acc[j];
        smem_[t] = r;
    }
    __syncthreads();

    // phase 4: c[t] = bout[t] + sum_k memory[k]*Wout[k][t]  (16 chains)
    {
        float acc[16];
        #pragma unroll
        for (int j = 0; j < 16; j++) acc[j] = 0.0f;
        #pragma unroll
        for (int k = 0; k < Dd; k += 16) {
            #pragma unroll
            for (int j = 0; j < 16; j++)
                acc[j] += smem_[k + j] * __ldg(&Wout[(size_t)(k + j) * Dd + t]);
        }
        float r = bout[t];
        #pragma unroll
        for (int j = 0; j < 16; j++) r += acc[j];
        g_c[b * Dd + t] = r;
    }
}

// ---------------- loss reduction + fused finalize ---------------------------
__global__ void loss_kernel(const int* __restrict__ vocab, float* __restrict__ out) {
    const int b = blockIdx.x;
    const int chunk = blockIdx.y;
    const int tid = threadIdx.x;
    const int w = tid >> 5, lane = tid & 31;
    const int len = g_len[b];
    const int nb = (len < Ss) ? len + 1 : Ss + 1;

    const float* crow = g_c + b * Dd + lane * 8;
    float4 c0 = *(const float4*)crow;
    float4 c1 = *(const float4*)(crow + 4);

    float ss = 0.0f;
    for (int s = chunk * 8 + w; s < nb; s += 64) {
        int u = (s == 0) ? BOS_T : vocab[b * Ss + s - 1];
        int v;
        if (s < len) v = vocab[b * Ss + s];
        else         v = (len < Ss) ? EOS_T : BOS_T;
        uint4 araw = *(const uint4*)(g_embWB + (size_t)u * Dd + lane * 8);
        uint4 traw = *(const uint4*)(g_embB  + (size_t)v * Dd + lane * 8);
        const __nv_bfloat162* ap = (const __nv_bfloat162*)&araw;
        const __nv_bfloat162* tp = (const __nv_bfloat162*)&traw;
        float2 f0 = __bfloat1622float2(ap[0]);
        float2 f1 = __bfloat1622float2(ap[1]);
        float2 f2 = __bfloat1622float2(ap[2]);
        float2 f3 = __bfloat1622float2(ap[3]);
        float2 t0 = __bfloat1622float2(tp[0]);
        float2 t1 = __bfloat1622float2(tp[1]);
        float2 t2 = __bfloat1622float2(tp[2]);
        float2 t3 = __bfloat1622float2(tp[3]);
        float d0 = f0.x + c0.x - t0.x; ss += d0 * d0;
        float d1 = f0.y + c0.y - t0.y; ss += d1 * d1;
        float d2 = f1.x + c0.z - t1.x; ss += d2 * d2;
        float d3 = f1.y + c0.w - t1.y; ss += d3 * d3;
        float d4 = f2.x + c1.x - t2.x; ss += d4 * d4;
        float d5 = f2.y + c1.y - t2.y; ss += d5 * d5;
        float d6 = f3.x + c1.z - t3.x; ss += d6 * d6;
        float d7 = f3.y + c1.w - t3.y; ss += d7 * d7;
    }
    #pragma unroll
    for (int off = 16; off > 0; off >>= 1)
        ss += __shfl_xor_sync(0xffffffffu, ss, off);
    __shared__ float swarp[8];
    if (lane == 0) swarp[w] = ss;
    __syncthreads();
    if (tid == 0) {
        double tot = 0.0;
        #pragma unroll
        for (int i = 0; i < 8; i++) tot += (double)swarp[i];
        atomicAdd(&g_sq, tot);
        __threadfence();
        int done = atomicAdd(&g_done, 1);
        if (done == Bb * 8 - 1) {
            double sq = atomicAdd(&g_sq, 0.0);
            double kl = atomicAdd(&g_kl, 0.0);
            int valid = atomicAdd(&g_valid, 0);
            long long denom = (long long)valid * (long long)Dd;
            if (denom < 1) denom = 1;
            out[0] = (float)(sq / (double)denom);
            out[1] = (float)(-0.5 * kl / (double)Bb);
        }
    }
}

// ---------------- launch ----------------------------------------------------
extern "C" void kernel_launch(void* const* d_in, const int* in_sizes, int n_in,
                              void* d_out, int out_size) {
    (void)in_sizes; (void)n_in; (void)out_size;
    const int*   vocab = (const int*)d_in[0];
    const int*   order = (const int*)d_in[1];
    const void*  mask  = d_in[2];
    const float* eps   = (const float*)d_in[3];
    const float* emb   = (const float*)d_in[4];
    const float* Wm    = (const float*)d_in[5];
    const float* bm    = (const float*)d_in[6];
    const float* Wv    = (const float*)d_in[7];
    const float* bv    = (const float*)d_in[8];
    const float* Wlin  = (const float*)d_in[9];
    const float* blin  = (const float*)d_in[10];
    const float* Wout  = (const float*)d_in[11];
    const float* bout  = (const float*)d_in[12];
    float* out = (float*)d_out;

    static cudaStream_t s2 = nullptr;
    static cudaEvent_t ev_fork = nullptr, ev_join = nullptr;
    static int configured = 0;
    if (!configured) {
        cudaFuncSetAttribute(gemm_mma, cudaFuncAttributeMaxDynamicSharedMemorySize, SMEM_GEMM);
        cudaStreamCreateWithFlags(&s2, cudaStreamNonBlocking);
        cudaEventCreateWithFlags(&ev_fork, cudaEventDisableTiming);
        cudaEventCreateWithFlags(&ev_join, cudaEventDisableTiming);
        configured = 1;
    }

    cudaEventRecord(ev_fork, 0);

    // main stream: GEMM path launched first so it leads the replay
    gemm_mma<<<(Vv + 127) / 128, 512, SMEM_GEMM>>>(emb, Wout);

    // side stream: k0 + enc chain (independent of GEMM)
    cudaStreamWaitEvent(s2, ev_fork, 0);
    k0_detect<<<64, 256, 0, s2>>>((const unsigned*)mask);
    enc_par<<<dim3(Bb, 8), 256, 0, s2>>>(vocab, order, mask, emb);
    klat_kernel<<<Bb, 256, 0, s2>>>(eps, Wm, bm, Wv, bv, Wlin, blin, Wout, bout);
    cudaEventRecord(ev_join, s2);

    cudaStreamWaitEvent(0, ev_join, 0);
    loss_kernel<<<dim3(Bb, 8), 256>>>(vocab, out);
}

// round 13
// speedup vs baseline: 1.4688x; 1.4083x over previous
#include <cuda_runtime.h>
#include <cuda_bf16.h>
#include <cstdint>

#define Bb 256
#define Ss 512
#define Vv 50000
#define Dd 256
#define Ll 128
#define PAD_T 0
#define BOS_T 1
#define EOS_T 2

#define ROWB 528                      // B row bytes (k-major row: 256 bf16 + pad)
#define AROW 144                      // A chunk row bytes (64 bf16 + pad)
#define ACH  (128 * AROW)             // 18432 per A buffer
#define B_BYTES (256 * ROWB)          // 135168
#define SMEM_GEMM (B_BYTES + 2 * ACH) // 172032
#define STG_ROW 144                   // epilogue staging row bytes

// ---------------- device scratch ----------------
__device__ __nv_bfloat16 g_embWB[(size_t)Vv * Dd];  // bf16 emb@Wout
__device__ __nv_bfloat16 g_embB[(size_t)Vv * Dd];   // bf16 emb
__device__ float  g_enc[Bb * Dd];
__device__ float  g_sv[Bb * Dd];                    // per-batch sum of (a - t)
__device__ float  g_c[Bb * Dd];
__device__ int    g_len[Bb];
__device__ int    g_mode;
__device__ int    g_valid;
__device__ int    g_done;
__device__ double g_sq;
__device__ double g_kl;

__device__ __forceinline__ uint32_t smem_u32(const void* p) {
    return (uint32_t)__cvta_generic_to_shared(p);
}

// ---------------- K0: detect mask dtype, zero enc/sv + accumulators ---------
__global__ void k0_detect(const unsigned* mask_words) {
    {
        int i = blockIdx.x * 256 + threadIdx.x;
        if (i < 16384)
            ((float4*)g_enc)[i] = make_float4(0.f, 0.f, 0.f, 0.f);
        else
            ((float4*)g_sv)[i - 16384] = make_float4(0.f, 0.f, 0.f, 0.f);
    }
    if (blockIdx.x != 0) return;
    __shared__ int any_gt1, any_f32;
    if (threadIdx.x == 0) { any_gt1 = 0; any_f32 = 0; }
    __syncthreads();
    int bad = 0, f32 = 0;
    for (int i = threadIdx.x; i < 32768; i += 256) {
        unsigned v = mask_words[i];
        if (v > 1u) { bad = 1; if (v == 0x3f800000u) f32 = 1; }
    }
    if (bad) atomicOr(&any_gt1, 1);
    if (f32) atomicOr(&any_f32, 1);
    __syncthreads();
    if (threadIdx.x == 0) {
        g_mode = any_gt1 ? (any_f32 ? 2 : 1) : 0;
        g_sq = 0.0; g_kl = 0.0; g_valid = 0; g_done = 0;
    }
}
__device__ __forceinline__ int mask_at(const void* m, int idx, int mode) {
    if (mode == 0) return ((const int*)m)[idx] != 0;
    if (mode == 1) return ((const unsigned char*)m)[idx] != 0;
    return ((const float*)m)[idx] != 0.0f;
}

// ---------------- gemm_mma: 512 thr, 16 warps, 32x64 warp tiles (R8) --------
__global__ __launch_bounds__(512, 1)
void gemm_mma(const float* __restrict__ emb, const float* __restrict__ Wout) {
    extern __shared__ char sm[];
    char* smB = sm;                 // [k=256][ROWB]
    char* smA = sm + B_BYTES;       // 2 x [128][AROW]

    const int tid  = threadIdx.x;
    const int wid  = tid >> 5, lane = tid & 31;
    const int row0 = blockIdx.x * 128;

    // ---- B fill: fp32 Wout -> bf16 smem (k-major), coalesced ----
    {
        #pragma unroll
        for (int j = 0; j < 32; j++) {
            int u = tid + j * 512;              // < 16384 float4s
            float4 x = ((const float4*)Wout)[u];
            int k  = u >> 6;
            int n0 = (u & 63) * 4;
            __nv_bfloat162 p0 = __floats2bfloat162_rn(x.x, x.y);
            __nv_bfloat162 p1 = __floats2bfloat162_rn(x.z, x.w);
            *(uint2*)(smB + k * ROWB + n0 * 2) = make_uint2(*(uint32_t*)&p0, *(uint32_t*)&p1);
        }
    }

    float4 stage[4];
    // ---- load chunk 0 ----
    #pragma unroll
    for (int j = 0; j < 4; j++) {
        int u = tid + j * 512;
        int r = u >> 4, q = u & 15;
        stage[j] = (row0 + r < Vv)
                 ? *(const float4*)(emb + (size_t)(row0 + r) * Dd + q * 4)
                 : make_float4(0.f, 0.f, 0.f, 0.f);
    }
    #pragma unroll
    for (int j = 0; j < 4; j++) {
        int u = tid + j * 512;
        int r = u >> 4, q = u & 15;
        __nv_bfloat162 p0 = __floats2bfloat162_rn(stage[j].x, stage[j].y);
        __nv_bfloat162 p1 = __floats2bfloat162_rn(stage[j].z, stage[j].w);
        uint2 pv = make_uint2(*(uint32_t*)&p0, *(uint32_t*)&p1);
        *(uint2*)(smA + r * AROW + q * 8) = pv;
        if (row0 + r < Vv)
            *(uint2*)(g_embB + (size_t)(row0 + r) * Dd + q * 4) = pv;
    }
    __syncthreads();

    const int wm = wid & 3, wn = wid >> 2;
    float acc[2][8][4];
    #pragma unroll
    for (int mt = 0; mt < 2; mt++)
        #pragma unroll
        for (int nt = 0; nt < 8; nt++)
            #pragma unroll
            for (int e = 0; e < 4; e++) acc[mt][nt][e] = 0.0f;

    const uint32_t aBase = smem_u32(smA) + (wm * 32 + (lane & 15)) * AROW + (lane >> 4) * 16;
    const uint32_t bBase = smem_u32(smB) + (lane & 15) * ROWB
                         + (wn * 64 + (lane >> 4) * 8) * 2;

    for (int c = 0; c < 4; c++) {
        if (c < 3) {
            #pragma unroll
            for (int j = 0; j < 4; j++) {
                int u = tid + j * 512;
                int r = u >> 4, q = u & 15;
                stage[j] = (row0 + r < Vv)
                         ? *(const float4*)(emb + (size_t)(row0 + r) * Dd + (c + 1) * 64 + q * 4)
                         : make_float4(0.f, 0.f, 0.f, 0.f);
            }
        }
        const uint32_t abuf = aBase + (c & 1) * ACH;
        const uint32_t bko  = (uint32_t)(c * 64) * ROWB;
        #pragma unroll
        for (int ks = 0; ks < 4; ks++) {
            uint32_t a[2][4];
            #pragma unroll
            for (int mt = 0; mt < 2; mt++)
                asm volatile("ldmatrix.sync.aligned.m8n8.x4.shared.b16 {%0,%1,%2,%3}, [%4];"
                             : "=r"(a[mt][0]), "=r"(a[mt][1]), "=r"(a[mt][2]), "=r"(a[mt][3])
                             : "r"(abuf + mt * 16 * AROW + ks * 32));
            #pragma unroll
            for (int np = 0; np < 4; np++) {
                uint32_t b0, b1, b2, b3;
                asm volatile("ldmatrix.sync.aligned.m8n8.x4.trans.shared.b16 {%0,%1,%2,%3}, [%4];"
                             : "=r"(b0), "=r"(b1), "=r"(b2), "=r"(b3)
                             : "r"(bBase + bko + ks * 16 * ROWB + np * 32));
                #pragma unroll
                for (int mt = 0; mt < 2; mt++) {
                    float* c0 = acc[mt][2 * np];
                    asm volatile("mma.sync.aligned.m16n8k16.row.col.f32.bf16.bf16.f32 "
                                 "{%0,%1,%2,%3}, {%4,%5,%6,%7}, {%8,%9}, {%0,%1,%2,%3};"
                                 : "+f"(c0[0]), "+f"(c0[1]), "+f"(c0[2]), "+f"(c0[3])
                                 : "r"(a[mt][0]), "r"(a[mt][1]), "r"(a[mt][2]), "r"(a[mt][3]),
                                   "r"(b0), "r"(b1));
                    float* c1 = acc[mt][2 * np + 1];
                    asm volatile("mma.sync.aligned.m16n8k16.row.col.f32.bf16.bf16.f32 "
                                 "{%0,%1,%2,%3}, {%4,%5,%6,%7}, {%8,%9}, {%0,%1,%2,%3};"
                                 : "+f"(c1[0]), "+f"(c1[1]), "+f"(c1[2]), "+f"(c1[3])
                                 : "r"(a[mt][0]), "r"(a[mt][1]), "r"(a[mt][2]), "r"(a[mt][3]),
                                   "r"(b2), "r"(b3));
                }
            }
        }
        if (c < 3) {
            __syncthreads();
            char* dst = smA + ((c + 1) & 1) * ACH;
            #pragma unroll
            for (int j = 0; j < 4; j++) {
                int u = tid + j * 512;
                int r = u >> 4, q = u & 15;
                __nv_bfloat162 p0 = __floats2bfloat162_rn(stage[j].x, stage[j].y);
                __nv_bfloat162 p1 = __floats2bfloat162_rn(stage[j].z, stage[j].w);
                uint2 pv = make_uint2(*(uint32_t*)&p0, *(uint32_t*)&p1);
                *(uint2*)(dst + r * AROW + q * 8) = pv;
                if (row0 + r < Vv)
                    *(uint2*)(g_embB + (size_t)(row0 + r) * Dd + (c + 1) * 64 + q * 4) = pv;
            }
            __syncthreads();
        }
    }

    // ---- epilogue: stage per-warp 32x64 bf16 tile in smem, dense stores ----
    {
        char* stg = smB + wid * 32 * STG_ROW;
        const int colq = (lane & 3) * 2;
        const int rowq = lane >> 2;
        #pragma unroll
        for (int mt = 0; mt < 2; mt++) {
            #pragma unroll
            for (int nt = 0; nt < 8; nt++) {
                __nv_bfloat162 lo = __floats2bfloat162_rn(acc[mt][nt][0], acc[mt][nt][1]);
                __nv_bfloat162 hi = __floats2bfloat162_rn(acc[mt][nt][2], acc[mt][nt][3]);
                *(uint32_t*)(stg + (mt * 16 + rowq) * STG_ROW + (nt * 8 + colq) * 2) = *(uint32_t*)&lo;
                *(uint32_t*)(stg + (mt * 16 + rowq + 8) * STG_ROW + (nt * 8 + colq) * 2) = *(uint32_t*)&hi;
            }
        }
        __syncwarp();
        #pragma unroll
        for (int p = 0; p < 8; p++) {
            int row = p * 4 + (lane >> 3);
            int q = lane & 7;
            uint4 v = *(const uint4*)(stg + row * STG_ROW + q * 16);
            int gr = row0 + wm * 32 + row;
            if (gr < Vv)
                *(uint4*)(g_embWB + (size_t)gr * Dd + wn * 64 + q * 8) = v;
        }
    }
}

// ---------------- enc_par: partial masked sums, grid (Bb, 8) ---------------
__global__ void enc_par(const int* __restrict__ vocab,
                        const int* __restrict__ order,
                        const void* __restrict__ mask,
                        const float* __restrict__ emb) {
    const int b = blockIdx.x;
    const int part = blockIdx.y;
    const int tid = threadIdx.x;
    const int w = tid >> 5, lane = tid & 31;
    const int mode = g_mode;

    __shared__ int sred[256];
    __shared__ int s_len;

    int cnt = 0;
    for (int i = tid; i < Ss; i += 256) cnt += mask_at(mask, b * Ss + i, mode);
    sred[tid] = cnt;
    __syncthreads();
    for (int st = 128; st > 0; st >>= 1) {
        if (tid < st) sred[tid] += sred[tid + st];
        __syncthreads();
    }
    if (tid == 0) {
        int len = sred[0];
        s_len = len;
        if (part == 0) {
            g_len[b] = len;
            atomicAdd(&g_valid, (len < Ss) ? len + 1 : Ss + 1);
        }
    }
    __syncthreads();
    const int len = s_len;

    float a0 = 0, a1 = 0, a2 = 0, a3 = 0, a4 = 0, a5 = 0, a6 = 0, a7 = 0;
    for (int s = part * 8 + w; s < len; s += 64) {
        int tok = vocab[b * Ss + s];
        int oi = order[(size_t)(b * Ss + s) * 6];
        if (oi == -1) oi = BOS_T;
        int p;
        if (s == 0) p = BOS_T;
        else        p = (oi < len) ? vocab[b * Ss + oi] : PAD_T;
        const float* r1 = emb + (size_t)tok * Dd + lane * 8;
        const float* r2 = emb + (size_t)p   * Dd + lane * 8;
        float4 x0 = *(const float4*)r1;
        float4 x1 = *(const float4*)(r1 + 4);
        float4 y0 = *(const float4*)r2;
        float4 y1 = *(const float4*)(r2 + 4);
        a0 += x0.x + y0.x; a1 += x0.y + y0.y; a2 += x0.z + y0.z; a3 += x0.w + y0.w;
        a4 += x1.x + y1.x; a5 += x1.y + y1.y; a6 += x1.z + y1.z; a7 += x1.w + y1.w;
    }
    __shared__ float s_acc[8][256];
    float* dst = &s_acc[w][lane * 8];
    dst[0] = a0; dst[1] = a1; dst[2] = a2; dst[3] = a3;
    dst[4] = a4; dst[5] = a5; dst[6] = a6; dst[7] = a7;
    __syncthreads();
    float v = 0;
    #pragma unroll
    for (int ww = 0; ww < 8; ww++) v += s_acc[ww][tid];
    atomicAdd(&g_enc[b * Dd + tid], v);
}

// ---------------- klat (R10-proven): fused mean/lv -> z,kl -> memory -> c ---
__global__ void klat_kernel(const float* __restrict__ eps,
                            const float* __restrict__ Wm, const float* __restrict__ bm,
                            const float* __restrict__ Wv, const float* __restrict__ bv,
                            const float* __restrict__ Wlin, const float* __restrict__ blin,
                            const float* __restrict__ Wout, const float* __restrict__ bout) {
    const int b = blockIdx.x, t = threadIdx.x;
    __shared__ float se[Dd];
    __shared__ float smean[Ll], slv[Ll], sz[Ll], smem_[Dd];
    __shared__ float skl[256];

    const float inv = 1.0f / (float)g_len[b];
    se[t] = g_enc[b * Dd + t] * inv;
    __syncthreads();

    {
        const int tt = t & (Ll - 1);
        const float* W = (t < Ll) ? Wm : Wv;
        float a0 = 0.f, a1 = 0.f, a2 = 0.f, a3 = 0.f;
        #pragma unroll
        for (int d = 0; d < Dd; d += 4) {
            a0 += se[d + 0] * W[(d + 0) * Ll + tt];
            a1 += se[d + 1] * W[(d + 1) * Ll + tt];
            a2 += se[d + 2] * W[(d + 2) * Ll + tt];
            a3 += se[d + 3] * W[(d + 3) * Ll + tt];
        }
        float r = ((t < Ll) ? bm[tt] : bv[tt]) + (a0 + a1) + (a2 + a3);
        if (t < Ll) smean[tt] = r; else slv[tt] = r;
    }
    __syncthreads();

    float klp = 0.0f;
    if (t < Ll) {
        float mean = smean[t], lv = slv[t];
        sz[t] = mean + eps[b * Ll + t] * expf(0.5f * lv);
        klp = 1.0f + lv - mean * mean - expf(lv);
    }
    skl[t] = klp;
    __syncthreads();
    for (int st = 128; st > 0; st >>= 1) {
        if (t < st) skl[t] += skl[t + st];
        __syncthreads();
    }
    if (t == 0) atomicAdd(&g_kl, (double)skl[0]);

    {
        float a0 = 0.f, a1 = 0.f, a2 = 0.f, a3 = 0.f;
        #pragma unroll
        for (int l = 0; l < Ll; l += 4) {
            a0 += sz[l + 0] * Wlin[(l + 0) * Dd + t];
            a1 += sz[l + 1] * Wlin[(l + 1) * Dd + t];
            a2 += sz[l + 2] * Wlin[(l + 2) * Dd + t];
            a3 += sz[l + 3] * Wlin[(l + 3) * Dd + t];
        }
        smem_[t] = blin[t] + (a0 + a1) + (a2 + a3);
    }
    __syncthreads();

    {
        float a0 = 0.f, a1 = 0.f, a2 = 0.f, a3 = 0.f;
        #pragma unroll
        for (int k = 0; k < Dd; k += 4) {
            a0 += smem_[k + 0] * Wout[(size_t)(k + 0) * Dd + t];
            a1 += smem_[k + 1] * Wout[(size_t)(k + 1) * Dd + t];
            a2 += smem_[k + 2] * Wout[(size_t)(k + 2) * Dd + t];
            a3 += smem_[k + 3] * Wout[(size_t)(k + 3) * Dd + t];
        }
        g_c[b * Dd + t] = bout[t] + (a0 + a1) + (a2 + a3);
    }
}

// ---------------- loss: Σ(a-t)² and per-batch vector Σ(a-t) — NO c ----------
__global__ void loss_kernel(const int* __restrict__ vocab) {
    const int b = blockIdx.x;
    const int chunk = blockIdx.y;   // 0..7
    const int tid = threadIdx.x;
    const int w = tid >> 5, lane = tid & 31;
    const int len = g_len[b];
    const int nb = (len < Ss) ? len + 1 : Ss + 1;

    float ss = 0.0f;
    float va[8] = {0.f, 0.f, 0.f, 0.f, 0.f, 0.f, 0.f, 0.f};
    for (int s = chunk * 8 + w; s < nb; s += 64) {
        int u = (s == 0) ? BOS_T : vocab[b * Ss + s - 1];
        int v;
        if (s < len) v = vocab[b * Ss + s];
        else         v = (len < Ss) ? EOS_T : BOS_T;
        uint4 araw = *(const uint4*)(g_embWB + (size_t)u * Dd + lane * 8);
        uint4 traw = *(const uint4*)(g_embB  + (size_t)v * Dd + lane * 8);
        const __nv_bfloat162* ap = (const __nv_bfloat162*)&araw;
        const __nv_bfloat162* tp = (const __nv_bfloat162*)&traw;
        #pragma unroll
        for (int k = 0; k < 4; k++) {
            float2 fa = __bfloat1622float2(ap[k]);
            float2 ft = __bfloat1622float2(tp[k]);
            float d0 = fa.x - ft.x;
            float d1 = fa.y - ft.y;
            ss += d0 * d0 + d1 * d1;
            va[2 * k]     += d0;
            va[2 * k + 1] += d1;
        }
    }
    // scalar warp-reduce
    #pragma unroll
    for (int off = 16; off > 0; off >>= 1)
        ss += __shfl_xor_sync(0xffffffffu, ss, off);
    __shared__ float swarp[8];
    if (lane == 0) swarp[w] = ss;
    // vector cross-warp reduce
    __shared__ float s_acc[8][256];
    float* dst = &s_acc[w][lane * 8];
    #pragma unroll
    for (int k = 0; k < 8; k++) dst[k] = va[k];
    __syncthreads();
    float vsum = 0.f;
    #pragma unroll
    for (int ww = 0; ww < 8; ww++) vsum += s_acc[ww][tid];
    atomicAdd(&g_sv[b * Dd + tid], vsum);
    if (tid == 0) {
        double tot = 0.0;
        #pragma unroll
        for (int i = 0; i < 8; i++) tot += (double)swarp[i];
        atomicAdd(&g_sq, tot);
    }
}

// ---------------- combine: fold c-terms + finalize --------------------------
__global__ void combine_kernel(float* __restrict__ out) {
    const int b = blockIdx.x, t = threadIdx.x;
    const int len = g_len[b];
    const float nb = (float)((len < Ss) ? len + 1 : Ss + 1);
    float c = g_c[b * Dd + t];
    float v = g_sv[b * Dd + t];
    float part = 2.0f * c * v + nb * c * c;
    #pragma unroll
    for (int off = 16; off > 0; off >>= 1)
        part += __shfl_xor_sync(0xffffffffu, part, off);
    __shared__ float sw[8];
    if ((t & 31) == 0) sw[t >> 5] = part;
    __syncthreads();
    if (t == 0) {
        double tot = 0.0;
        #pragma unroll
        for (int i = 0; i < 8; i++) tot += (double)sw[i];
        atomicAdd(&g_sq, tot);
        __threadfence();
        int done = atomicAdd(&g_done, 1);
        if (done == Bb - 1) {
            double sq = atomicAdd(&g_sq, 0.0);
            double kl = atomicAdd(&g_kl, 0.0);
            int valid = atomicAdd(&g_valid, 0);
            long long denom = (long long)valid * (long long)Dd;
            if (denom < 1) denom = 1;
            out[0] = (float)(sq / (double)denom);
            out[1] = (float)(-0.5 * kl / (double)Bb);
        }
    }
}

// ---------------- launch ----------------------------------------------------
extern "C" void kernel_launch(void* const* d_in, const int* in_sizes, int n_in,
                              void* d_out, int out_size) {
    (void)in_sizes; (void)n_in; (void)out_size;
    const int*   vocab = (const int*)d_in[0];
    const int*   order = (const int*)d_in[1];
    const void*  mask  = d_in[2];
    const float* eps   = (const float*)d_in[3];
    const float* emb   = (const float*)d_in[4];
    const float* Wm    = (const float*)d_in[5];
    const float* bm    = (const float*)d_in[6];
    const float* Wv    = (const float*)d_in[7];
    const float* bv    = (const float*)d_in[8];
    const float* Wlin  = (const float*)d_in[9];
    const float* blin  = (const float*)d_in[10];
    const float* Wout  = (const float*)d_in[11];
    const float* bout  = (const float*)d_in[12];
    float* out = (float*)d_out;

    static cudaStream_t s2 = nullptr;
    static cudaEvent_t ev_fork = nullptr, ev_enc = nullptr, ev_klat = nullptr;
    static int configured = 0;
    if (!configured) {
        cudaFuncSetAttribute(gemm_mma, cudaFuncAttributeMaxDynamicSharedMemorySize, SMEM_GEMM);
        cudaStreamCreateWithFlags(&s2, cudaStreamNonBlocking);
        cudaEventCreateWithFlags(&ev_fork, cudaEventDisableTiming);
        cudaEventCreateWithFlags(&ev_enc, cudaEventDisableTiming);
        cudaEventCreateWithFlags(&ev_klat, cudaEventDisableTiming);
        configured = 1;
    }

    cudaEventRecord(ev_fork, 0);

    // main stream: GEMM leads
    gemm_mma<<<(Vv + 127) / 128, 512, SMEM_GEMM>>>(emb, Wout);

    // side stream: k0 -> enc -> klat
    cudaStreamWaitEvent(s2, ev_fork, 0);
    k0_detect<<<128, 256, 0, s2>>>((const unsigned*)mask);
    enc_par<<<dim3(Bb, 8), 256, 0, s2>>>(vocab, order, mask, emb);
    cudaEventRecord(ev_enc, s2);
    klat_kernel<<<Bb, 256, 0, s2>>>(eps, Wm, bm, Wv, bv, Wlin, blin, Wout, bout);
    cudaEventRecord(ev_klat, s2);

    // main: loss needs gemm + enc (g_len, zeroed g_sv) — NOT klat
    cudaStreamWaitEvent(0, ev_enc, 0);
    loss_kernel<<<dim3(Bb, 8), 256>>>(vocab);
    // combine needs klat (g_c) + loss (g_sv, g_sq partials)
    cudaStreamWaitEvent(0, ev_klat, 0);
    combine_kernel<<<Bb, 256>>>(out);
}